// round 9
// baseline (speedup 1.0000x reference)
#include <cuda_runtime.h>
#include <cuda_bf16.h>
#include <cstdint>

#define N_NODES_MAX 100000
#define MASK_WORDS ((N_NODES_MAX + 31) / 32)
#define DSIGMA_DT (-0.0001f)
#define PHI_THRESH 0.3f
#define EPS 1e-8f

// Packed {pos.x, pos.y, pos.z, T} per node; accumulator {num.xyz, cnt};
// interface-mask bitmap (1 bit per node).
__device__ float4 g_packed[N_NODES_MAX];
__device__ float4 g_acc[N_NODES_MAX];
__device__ unsigned g_mask[MASK_WORDS];
__device__ int g_idx_is64;

// Smem-staged prep: each block owns 256 nodes. Dense coalesced reads of the
// x slab (2304 floats) and pos slab (768 floats) into smem, then per-node
// extraction (stride 9 / stride 3 -> conflict-free, coprime with 32 banks).
// All strided/sectored DRAM access patterns eliminated.
__global__ __launch_bounds__(256) void prep_kernel(
        const float* __restrict__ x,
        const float* __restrict__ pos,
        const unsigned int* __restrict__ ei_words,
        int n_nodes) {
    __shared__ float sx[256 * 9];
    __shared__ float sp[256 * 3];

    const int t = threadIdx.x;
    const int base = blockIdx.x * 256;
    const int count = min(256, n_nodes - base);
    if (count <= 0) return;

    const int xbeg = base * 9, xlen = count * 9;
    #pragma unroll
    for (int j = 0; j < 9; j++) {
        int off = j * 256 + t;
        if (off < xlen) sx[off] = x[xbeg + off];
    }
    const int pbeg = base * 3, plen = count * 3;
    #pragma unroll
    for (int j = 0; j < 3; j++) {
        int off = j * 256 + t;
        if (off < plen) sp[off] = pos[pbeg + off];
    }
    __syncthreads();

    unsigned bit = 0;
    if (t < count) {
        int i = base + t;
        float T   = sx[t * 9 + 3];
        float phi = sx[t * 9 + 8];
        g_packed[i] = make_float4(sp[t * 3 + 0], sp[t * 3 + 1], sp[t * 3 + 2], T);
        g_acc[i] = make_float4(0.f, 0.f, 0.f, 0.f);
        bit = (fabsf(phi) < PHI_THRESH) ? 1u : 0u;
    }
    unsigned word = __ballot_sync(0xFFFFFFFFu, bit);
    if ((t & 31) == 0 && (base + t) < n_nodes) {
        g_mask[(base + t) >> 5] = word;
    }

    if (base == 0 && t == 0) {
        // int64 little-endian with values < 2^31 => odd 32-bit words all zero.
        unsigned int acc = 0;
        #pragma unroll
        for (int k = 0; k < 64; k++) acc |= ei_words[2 * k + 1];
        g_idx_is64 = (acc == 0) ? 1 : 0;
    }
}

// Grid-stride edge scatter with shared-memory mask bitmap.
// Plain (cache-default) index loads: the full working set (~60MB) fits in
// the 126MB L2, so the index stream stays L2-resident across graph replays.
__global__ __launch_bounds__(512) void edge_scatter_kernel(
        const void* __restrict__ edge_index, int n_edges, int mask_words) {
    __shared__ unsigned smask[MASK_WORDS];
    for (int w = threadIdx.x; w < mask_words; w += blockDim.x)
        smask[w] = g_mask[w];
    __syncthreads();

    const int stride = gridDim.x * blockDim.x;
    const int start = blockIdx.x * blockDim.x + threadIdx.x;
    const int is64 = g_idx_is64;

    if (is64) {
        const long long* ei = (const long long*)edge_index;
        for (int e = start; e < n_edges; e += stride) {
            int d = (int)ei[n_edges + e];
            if ((smask[d >> 5] >> (d & 31)) & 1u) {
                int s = (int)ei[e];
                float4 a = __ldg(&g_packed[s]);
                float4 b = __ldg(&g_packed[d]);
                float dT = a.w - b.w;
                float px = a.x - b.x, py = a.y - b.y, pz = a.z - b.z;
                float w = dT / (px * px + py * py + pz * pz + EPS);
                float4* addr = &g_acc[d];
                asm volatile("red.global.add.v4.f32 [%0], {%1, %2, %3, %4};"
                             :: "l"(addr), "f"(w * px), "f"(w * py), "f"(w * pz), "f"(1.0f)
                             : "memory");
            }
        }
    } else {
        const int* ei = (const int*)edge_index;
        for (int e = start; e < n_edges; e += stride) {
            int d = ei[n_edges + e];
            if ((smask[d >> 5] >> (d & 31)) & 1u) {
                int s = ei[e];
                float4 a = __ldg(&g_packed[s]);
                float4 b = __ldg(&g_packed[d]);
                float dT = a.w - b.w;
                float px = a.x - b.x, py = a.y - b.y, pz = a.z - b.z;
                float w = dT / (px * px + py * py + pz * pz + EPS);
                float4* addr = &g_acc[d];
                asm volatile("red.global.add.v4.f32 [%0], {%1, %2, %3, %4};"
                             :: "l"(addr), "f"(w * px), "f"(w * py), "f"(w * pz), "f"(1.0f)
                             : "memory");
            }
        }
    }
}

__global__ __launch_bounds__(256) void finalize_kernel(
        float* __restrict__ out, int n_nodes) {
    int i = blockIdx.x * blockDim.x + threadIdx.x;
    if (i >= n_nodes) return;

    unsigned bit = (g_mask[i >> 5] >> (i & 31)) & 1u;
    float4 a = g_acc[i];

    float cnt = fmaxf(a.w, 1.0f);
    float s = bit ? (DSIGMA_DT / cnt) : 0.0f;

    out[i * 3 + 0] = s * a.x;
    out[i * 3 + 1] = s * a.y;
    out[i * 3 + 2] = s * a.z;
}

extern "C" void kernel_launch(void* const* d_in, const int* in_sizes, int n_in,
                              void* d_out, int out_size) {
    const float* x = (const float*)d_in[0];    // [N, 9]
    const float* pos = (const float*)d_in[1];  // [N, 3]
    const void* edge_index = d_in[2];          // [2, E] int32 or int64

    int n_nodes = in_sizes[1] / 3;
    int n_edges = in_sizes[2] / 2;
    int mask_words = (n_nodes + 31) / 32;
    float* out = (float*)d_out;

    prep_kernel<<<(n_nodes + 255) / 256, 256>>>(
        x, pos, (const unsigned int*)edge_index, n_nodes);

    int eblocks = (n_edges + 511) / 512;
    if (eblocks > 592) eblocks = 592;   // ~4 blocks/SM, grid-stride
    edge_scatter_kernel<<<eblocks, 512>>>(edge_index, n_edges, mask_words);

    finalize_kernel<<<(n_nodes + 255) / 256, 256>>>(out, n_nodes);
}